// round 5
// baseline (speedup 1.0000x reference)
#include <cuda_runtime.h>
#include <cuda_fp16.h>
#include <cstdint>

#define B_SZ    8192
#define DK      128
#define BM      128
#define BN      128
#define EPSV    1e-6f
#define CEPS    (128.0f * 1e-6f * 1e-6f)
#define MARGINF 0.2f

// SMEM: four half tiles 128 x 136 (stride 136 halfs = 272B -> row start bank = 4*row mod 32)
#define HSTRIDE    136
#define HTILE_B    (128 * HSTRIDE * 2)     // 34816 bytes
#define SM_TGT     0                       // 128 bytes
#define SM_N2      128                     // 512 bytes
#define SM_AH      1024
#define SM_AL      (SM_AH + HTILE_B)
#define SM_BH      (SM_AL + HTILE_B)
#define SM_BL      (SM_BH + HTILE_B)
#define SMEM_TOTAL (SM_BL + HTILE_B)       // 140288

__device__ float    g_n1[B_SZ];
__device__ float    g_n2[B_SZ];
__device__ unsigned g_posmax[B_SZ];   // float bits; values >= 0 so uint order == float order
__device__ unsigned g_negmin[B_SZ];
__device__ char     g_tgt[B_SZ];
__device__ int      g_is32;

// ---------------------------------------------------------------------------
// Kernel 0: detect target dtype. View buffer as uint32[8192] (in-bounds for
// both int32[8192] and int64[8192]). int64 -> all odd words are 0 (values are
// 0/1). int32 -> odd words hold random 0/1 targets; all-zero has prob 2^-4096.
// ---------------------------------------------------------------------------
__global__ void detect_kernel(const unsigned* __restrict__ w) {
    __shared__ unsigned sred[32];
    unsigned acc = 0;
    for (int i = threadIdx.x; i < B_SZ / 2; i += 1024) acc |= w[2 * i + 1];
#pragma unroll
    for (int o = 16; o; o >>= 1) acc |= __shfl_xor_sync(0xFFFFFFFFu, acc, o);
    if ((threadIdx.x & 31) == 0) sred[threadIdx.x >> 5] = acc;
    __syncthreads();
    if (threadIdx.x < 32) {
        acc = sred[threadIdx.x];
#pragma unroll
        for (int o = 16; o; o >>= 1) acc |= __shfl_xor_sync(0xFFFFFFFFu, acc, o);
        if (threadIdx.x == 0) g_is32 = (acc != 0);
    }
}

// ---------------------------------------------------------------------------
// Kernel 1: row norms (+eps linear terms), init reduction arrays, decode target.
// ---------------------------------------------------------------------------
__global__ void norms_kernel(const float* __restrict__ e1, const float* __restrict__ e2,
                             const unsigned* __restrict__ tw) {
    int w   = threadIdx.x >> 5;
    int lid = threadIdx.x & 31;
    int r   = blockIdx.x * 8 + w;
    if (r >= B_SZ) return;

    float4 a = ((const float4*)(e1 + (size_t)r * DK))[lid];
    float4 b = ((const float4*)(e2 + (size_t)r * DK))[lid];
    float s1 = a.x + a.y + a.z + a.w;
    float q1 = a.x * a.x + a.y * a.y + a.z * a.z + a.w * a.w;
    float s2 = b.x + b.y + b.z + b.w;
    float q2 = b.x * b.x + b.y * b.y + b.z * b.z + b.w * b.w;
#pragma unroll
    for (int o = 16; o; o >>= 1) {
        s1 += __shfl_xor_sync(0xFFFFFFFFu, s1, o);
        q1 += __shfl_xor_sync(0xFFFFFFFFu, q1, o);
        s2 += __shfl_xor_sync(0xFFFFFFFFu, s2, o);
        q2 += __shfl_xor_sync(0xFFFFFFFFu, q2, o);
    }
    if (lid == 0) {
        g_n1[r] = q1 + 2.0f * EPSV * s1;
        g_n2[r] = q2 - 2.0f * EPSV * s2;
        g_posmax[r] = 0u;           // float 0.0
        g_negmin[r] = 0x7f800000u;  // +inf
        g_tgt[r] = (char)(g_is32 ? tw[r] : tw[2 * r]);
    }
}

// split a float4 into hi (fp16) and lo (fp16 of residual), packed as half2 pairs
__device__ __forceinline__ void split4(float4 f, uint32_t hi[2], uint32_t lo[2]) {
    __half hx = __float2half_rn(f.x), hy = __float2half_rn(f.y);
    __half hz = __float2half_rn(f.z), hw = __float2half_rn(f.w);
    __half lx = __float2half_rn(f.x - __half2float(hx));
    __half ly = __float2half_rn(f.y - __half2float(hy));
    __half lz = __float2half_rn(f.z - __half2float(hz));
    __half lw = __float2half_rn(f.w - __half2float(hw));
    __half2 h0 = __halves2half2(hx, hy), h1 = __halves2half2(hz, hw);
    __half2 l0 = __halves2half2(lx, ly), l1 = __halves2half2(lz, lw);
    hi[0] = *(uint32_t*)&h0; hi[1] = *(uint32_t*)&h1;
    lo[0] = *(uint32_t*)&l0; lo[1] = *(uint32_t*)&l1;
}

#define MMA16(C, A, Bv)                                                         \
    asm volatile(                                                               \
        "mma.sync.aligned.m16n8k16.row.col.f32.f16.f16.f32 "                    \
        "{%0,%1,%2,%3}, {%4,%5,%6,%7}, {%8,%9}, {%0,%1,%2,%3};"                 \
        : "+f"((C)[0]), "+f"((C)[1]), "+f"((C)[2]), "+f"((C)[3])                \
        : "r"((A)[0]), "r"((A)[1]), "r"((A)[2]), "r"((A)[3]),                   \
          "r"((Bv)[0]), "r"((Bv)[1]))

// ---------------------------------------------------------------------------
// Kernel 2: fused fp16x3 HMMA GEMM tile (128x128x128) + masked row max/min.
// 8 warps: wm = w%4 -> rows [wm*32,+32), wn = w/4 -> cols [wn*64,+64).
// ---------------------------------------------------------------------------
__global__ void __launch_bounds__(256, 1)
mma_kernel(const float* __restrict__ e1, const float* __restrict__ e2) {
    extern __shared__ char smem[];
    char*  tg  = (char*)(smem + SM_TGT);
    float* n2s = (float*)(smem + SM_N2);

    int tid = threadIdx.x;
    int w   = tid >> 5;
    int lid = tid & 31;
    int tq  = lid >> 2;     // lane / 4
    int tr  = lid & 3;      // lane % 4
    int wm  = w & 3;
    int wn  = w >> 2;
    int r0  = blockIdx.y * BM;
    int c0  = blockIdx.x * BN;

    if (tid < 128) {
        tg[tid]  = g_tgt[c0 + tid];
        n2s[tid] = g_n2[c0 + tid];
    }

    // Load + split tiles: 4096 float4 groups per matrix, A and B together.
    for (int g = tid; g < 4096; g += 256) {
        int row = g >> 5;            // 0..127
        int kc  = (g & 31) * 4;      // 0..124 step 4
        uint32_t off = (uint32_t)row * (HSTRIDE * 2) + kc * 2;   // bytes within tile

        float4 fa = *(const float4*)(e1 + (size_t)(r0 + row) * DK + kc);
        uint32_t ah[2], al[2];
        split4(fa, ah, al);
        *(uint2*)(smem + SM_AH + off) = make_uint2(ah[0], ah[1]);
        *(uint2*)(smem + SM_AL + off) = make_uint2(al[0], al[1]);

        float4 fb = *(const float4*)(e2 + (size_t)(c0 + row) * DK + kc);
        uint32_t bh[2], bl[2];
        split4(fb, bh, bl);
        *(uint2*)(smem + SM_BH + off) = make_uint2(bh[0], bh[1]);
        *(uint2*)(smem + SM_BL + off) = make_uint2(bl[0], bl[1]);
    }
    __syncthreads();

    float c[2][8][4];
#pragma unroll
    for (int mt = 0; mt < 2; mt++)
#pragma unroll
        for (int nt = 0; nt < 8; nt++)
#pragma unroll
            for (int i = 0; i < 4; i++) c[mt][nt][i] = 0.0f;

    const uint32_t* sAH = (const uint32_t*)(smem + SM_AH);
    const uint32_t* sAL = (const uint32_t*)(smem + SM_AL);
    const uint32_t* sBH = (const uint32_t*)(smem + SM_BH);
    const uint32_t* sBL = (const uint32_t*)(smem + SM_BL);
    int aRow = wm * 32 + tq;
    int bRow = wn * 64 + tq;

#pragma unroll
    for (int ks = 0; ks < 8; ks++) {
        int kw = ks * 8 + tr;        // word index of first element pair
        uint32_t ah[2][4], al[2][4], bh[8][2], bl[8][2];
#pragma unroll
        for (int mt = 0; mt < 2; mt++) {
            uint32_t o0 = (uint32_t)(aRow + mt * 16) * 68 + kw;
            uint32_t o1 = o0 + 8 * 68;
            ah[mt][0] = sAH[o0];     ah[mt][1] = sAH[o1];
            ah[mt][2] = sAH[o0 + 4]; ah[mt][3] = sAH[o1 + 4];
            al[mt][0] = sAL[o0];     al[mt][1] = sAL[o1];
            al[mt][2] = sAL[o0 + 4]; al[mt][3] = sAL[o1 + 4];
        }
#pragma unroll
        for (int nt = 0; nt < 8; nt++) {
            uint32_t o = (uint32_t)(bRow + nt * 8) * 68 + kw;
            bh[nt][0] = sBH[o]; bh[nt][1] = sBH[o + 4];
            bl[nt][0] = sBL[o]; bl[nt][1] = sBL[o + 4];
        }
#pragma unroll
        for (int mt = 0; mt < 2; mt++)
#pragma unroll
            for (int nt = 0; nt < 8; nt++) {
                MMA16(c[mt][nt], ah[mt], bh[nt]);
                MMA16(c[mt][nt], ah[mt], bl[nt]);
                MMA16(c[mt][nt], al[mt], bh[nt]);
            }
    }

    // Epilogue: 4 row-slots per thread: row = wm*32 + (s>>1)*16 + tq + (s&1)*8
    float n1v[4], maxp[4], minn[4];
#pragma unroll
    for (int s = 0; s < 4; s++) {
        int grow = r0 + wm * 32 + (s >> 1) * 16 + tq + (s & 1) * 8;
        n1v[s]  = g_n1[grow];
        maxp[s] = 0.0f;
        minn[s] = __int_as_float(0x7f800000);
    }
#pragma unroll
    for (int mt = 0; mt < 2; mt++)
#pragma unroll
        for (int nt = 0; nt < 8; nt++) {
            int j0 = wn * 64 + nt * 8 + tr * 2;
#pragma unroll
            for (int i = 0; i < 4; i++) {
                int s = mt * 2 + (i >> 1);
                int j = j0 + (i & 1);
                float sq = fmaxf(n1v[s] + n2s[j] - 2.0f * c[mt][nt][i] + CEPS, 0.0f);
                if (tg[j]) maxp[s] = fmaxf(maxp[s], sq);
                else       minn[s] = fminf(minn[s], sq);
            }
        }
#pragma unroll
    for (int s = 0; s < 4; s++) {
#pragma unroll
        for (int o = 1; o <= 2; o <<= 1) {
            maxp[s] = fmaxf(maxp[s], __shfl_xor_sync(0xFFFFFFFFu, maxp[s], o));
            minn[s] = fminf(minn[s], __shfl_xor_sync(0xFFFFFFFFu, minn[s], o));
        }
        if (tr == 0) {
            int grow = r0 + wm * 32 + (s >> 1) * 16 + tq + (s & 1) * 8;
            atomicMax(&g_posmax[grow], __float_as_uint(maxp[s]));
            atomicMin(&g_negmin[grow], __float_as_uint(minn[s]));
        }
    }
}

// ---------------------------------------------------------------------------
// Kernel 3: final scalar reduction over anchors (target == 1).
// ---------------------------------------------------------------------------
__global__ void final_kernel(float* __restrict__ out) {
    __shared__ float ss[32];
    __shared__ float sc[32];
    int tid = threadIdx.x;
    float s = 0.0f, c = 0.0f;
    for (int i = tid; i < B_SZ; i += 1024) {
        if (g_tgt[i]) {
            float pm = __uint_as_float(g_posmax[i]);
            float nm = __uint_as_float(g_negmin[i]);
            float v  = sqrtf(pm) - sqrtf(nm) + MARGINF;  // nm==inf -> v=-inf -> clamped 0
            s += fmaxf(v, 0.0f);
            c += 1.0f;
        }
    }
#pragma unroll
    for (int o = 16; o; o >>= 1) {
        s += __shfl_xor_sync(0xFFFFFFFFu, s, o);
        c += __shfl_xor_sync(0xFFFFFFFFu, c, o);
    }
    if ((tid & 31) == 0) { ss[tid >> 5] = s; sc[tid >> 5] = c; }
    __syncthreads();
    if (tid < 32) {
        s = ss[tid];
        c = sc[tid];
#pragma unroll
        for (int o = 16; o; o >>= 1) {
            s += __shfl_xor_sync(0xFFFFFFFFu, s, o);
            c += __shfl_xor_sync(0xFFFFFFFFu, c, o);
        }
        if (tid == 0) out[0] = s / c;
    }
}

extern "C" void kernel_launch(void* const* d_in, const int* in_sizes, int n_in,
                              void* d_out, int out_size) {
    const float*    e1 = (const float*)d_in[0];
    const float*    e2 = (const float*)d_in[1];
    const unsigned* tw = (const unsigned*)d_in[2];
    float* out = (float*)d_out;

    cudaFuncSetAttribute(mma_kernel, cudaFuncAttributeMaxDynamicSharedMemorySize, SMEM_TOTAL);

    detect_kernel<<<1, 1024>>>(tw);
    norms_kernel<<<B_SZ / 8, 256>>>(e1, e2, tw);
    mma_kernel<<<dim3(B_SZ / BN, B_SZ / BM), 256, SMEM_TOTAL>>>(e1, e2);
    final_kernel<<<1, 1024>>>(out);
}